// round 6
// baseline (speedup 1.0000x reference)
#include <cuda_runtime.h>
#include <cuda_fp16.h>
#include <cstdint>

#define B_    4
#define CIN   256
#define HH    64
#define WW    64
#define COUT  256
#define K2    9
#define NPIX  4096
#define NCHUNK 72               // 8 ci32-chunks * 9 k2, order: c32 outer, k2 inner
#define SROW  40                // floats per smem row (160B): conflict-free LDS.64

// ---------------- scratch ----------------
__device__ __align__(16) __half   g_xh[B_ * NPIX * CIN];     // x NHWC fp16
__device__ __align__(16) uint32_t g_wt[NCHUNK * 8192];       // W tf32: [ch][co256][k32 permuted]
__device__ __align__(16) int4     g_sidx[B_ * K2 * NPIX];    // corner bases in uint4-row units (pix*32)
__device__ __align__(16) float4   g_swt [B_ * K2 * NPIX];

__device__ __forceinline__ uint32_t smem_u32(const void* p) {
    uint32_t a;
    asm("{ .reg .u64 t; cvta.to.shared.u64 t, %1; cvt.u32.u64 %0, t; }" : "=r"(a) : "l"(p));
    return a;
}
__device__ __forceinline__ uint32_t f2tf32(float v) {
    uint32_t t;
    asm("cvt.rna.tf32.f32 %0, %1;" : "=r"(t) : "f"(v));
    return t;
}
__device__ __forceinline__ void mma_tf32(float* c, const uint32_t* a, const uint32_t* b) {
    asm volatile("mma.sync.aligned.m16n8k8.row.col.f32.tf32.tf32.f32 "
        "{%0,%1,%2,%3}, {%4,%5,%6,%7}, {%8,%9}, {%0,%1,%2,%3};"
        : "+f"(c[0]), "+f"(c[1]), "+f"(c[2]), "+f"(c[3])
        : "r"(a[0]), "r"(a[1]), "r"(a[2]), "r"(a[3]), "r"(b[0]), "r"(b[1]));
}
__device__ __forceinline__ void h8_to_f(uint4 u, float* f) {
    const __half2* h = (const __half2*)&u;
#pragma unroll
    for (int i = 0; i < 4; i++) {
        float2 t = __half22float2(h[i]);
        f[2 * i] = t.x;
        f[2 * i + 1] = t.y;
    }
}

// ---------------------------------------------------------------------------
// Prep 1: x NCHW -> NHWC fp16
__global__ void k_prep_x(const float* __restrict__ x) {
    __shared__ float tile[32][33];
    int b = blockIdx.z, p0 = blockIdx.x * 32, c0 = blockIdx.y * 32;
    int tx = threadIdx.x, ty = threadIdx.y;
#pragma unroll
    for (int i = ty; i < 32; i += 8)
        tile[i][tx] = x[(b * CIN + c0 + i) * NPIX + p0 + tx];
    __syncthreads();
#pragma unroll
    for (int i = ty; i < 32; i += 8)
        g_xh[(b * NPIX + p0 + i) * CIN + c0 + tx] = __float2half_rn(tile[tx][i]);
}

// Prep 2: W -> tf32 chunks [ch][co][k32], k PERMUTED within each 8-group:
// pos = ksg*8 + 2*(kg&3) + (kg>>2). Same permutation applied to A.
__global__ void k_prep_w(const float* __restrict__ w) {
    int ch  = blockIdx.x;
    int c32 = ch / 9, k2 = ch - c32 * 9;
    uint32_t* dst = g_wt + ch * 8192;
    for (int e = threadIdx.x; e < 8192; e += 256) {
        int r = e >> 5, j = e & 31;          // co, k-within-chunk
        int kg = j & 7, ksg = j >> 3;
        int pos = ksg * 8 + 2 * (kg & 3) + (kg >> 2);
        float v = w[(r * CIN + c32 * 32 + j) * K2 + k2];
        dst[r * 32 + pos] = f2tf32(v);
    }
}

// Prep 3: sampling params (corner bases in uint4-row units, folded weights)
__global__ void k_prep_params(const float* __restrict__ offset,
                              const float* __restrict__ mask) {
    int t = blockIdx.x * blockDim.x + threadIdx.x;
    int b  = t / (K2 * NPIX);
    int r  = t - b * (K2 * NPIX);
    int k2 = r >> 12;
    int p  = r & (NPIX - 1);
    int ho = p >> 6, wo = p & 63;
    int ky = k2 / 3, kx = k2 - ky * 3;

    float dy_off = offset[(b * 2 * K2 + 2 * k2    ) * NPIX + p];
    float dx_off = offset[(b * 2 * K2 + 2 * k2 + 1) * NPIX + p];
    float m      = mask  [(b * K2 + k2) * NPIX + p];

    float yf = (float)(ky + ho - 1) + dy_off;
    float xf = (float)(kx + wo - 1) + dx_off;
    float y0f = floorf(yf), x0f = floorf(xf);
    float dy = yf - y0f, dx = xf - x0f;
    int y0 = (int)y0f, x0 = (int)x0f;
    int y1 = y0 + 1,   x1 = x0 + 1;

    float w00 = (1.f - dy) * (1.f - dx) * m;
    float w01 = (1.f - dy) * dx * m;
    float w10 = dy * (1.f - dx) * m;
    float w11 = dy * dx * m;
    bool vy0 = (y0 >= 0) & (y0 < HH), vy1 = (y1 >= 0) & (y1 < HH);
    bool vx0 = (x0 >= 0) & (x0 < WW), vx1 = (x1 >= 0) & (x1 < WW);
    if (!(vy0 & vx0)) w00 = 0.f;
    if (!(vy0 & vx1)) w01 = 0.f;
    if (!(vy1 & vx0)) w10 = 0.f;
    if (!(vy1 & vx1)) w11 = 0.f;

    int y0c = min(max(y0, 0), HH - 1), y1c = min(max(y1, 0), HH - 1);
    int x0c = min(max(x0, 0), WW - 1), x1c = min(max(x1, 0), WW - 1);
    int base = b * NPIX;
    // pixel row in uint4 units: pix * (CIN halves / 8) = pix * 32
    g_sidx[t] = make_int4((base + y0c * WW + x0c) * 32,
                          (base + y0c * WW + x1c) * 32,
                          (base + y1c * WW + x0c) * 32,
                          (base + y1c * WW + x1c) * 32);
    g_swt[t] = make_float4(w00, w01, w10, w11);
}

// ---------------------------------------------------------------------------
// Main: TF32 mma.sync implicit GEMM. CTA: 64px x 256co, K=2304 in 72 chunks.
// grid 256, block 256 (8 warps), warp tile 32px x 64co, 2 CTAs/SM.
// A double-buffered (2x10KB), W double-buffered (2x40KB), params via LDG.
// ---------------------------------------------------------------------------
// floats: A0 0 | A1 2560 | W0 5120 | W1 15360 | sB 25600 | end 25856
#define SMEM_DYN 103424

__global__ __launch_bounds__(256, 2)
void k_conv(const float* __restrict__ bias, float* __restrict__ out) {
    extern __shared__ float dsm[];
    float*  A_s[2] = { dsm,        dsm + 2560 };
    float*  W_s[2] = { dsm + 5120, dsm + 15360 };
    float*  sB = dsm + 25600;

    int tid  = threadIdx.x;
    int b    = blockIdx.x >> 6;
    int p0   = (blockIdx.x & 63) * 64;
    int warp = tid >> 5, lane = tid & 31;

    sB[tid] = bias[tid];

    // ---- per-thread mappings ----
    int ty = lane >> 2, tk = lane & 3;        // mma frag coords
    int wm = warp >> 2, wn = warp & 3;        // warp tile: px wm*32, co wn*64
    int pl_b = tid >> 2, ksg_b = tid & 3;     // A-build: pixel, k-group-of-8
    const uint4* Xh = (const uint4*)g_xh;

    float acc[2][8][4];
#pragma unroll
    for (int i = 0; i < 2; i++)
#pragma unroll
        for (int j = 0; j < 8; j++)
#pragma unroll
            for (int q = 0; q < 4; q++) acc[i][j][q] = 0.f;

    // ---- builders ----
    auto build_W = [&](int ch, int s) {
        const char* src = (const char*)(g_wt + ch * 8192);
        uint32_t dst = smem_u32(W_s[s]);
#pragma unroll
        for (int i = 0; i < 8; i++) {
            int lin = tid + i * 256;             // 0..2047
            int co = lin >> 3, seg = lin & 7;    // 16B segment of row co
            uint32_t d = dst + (uint32_t)(co * 160 + seg * 16);
            const char* gp = src + (size_t)lin * 16;
            asm volatile("cp.async.cg.shared.global [%0], [%1], 16;" :: "r"(d), "l"(gp));
        }
        asm volatile("cp.async.commit_group;" ::: "memory");
    };
    auto build_A = [&](int ch, int s) {
        int c32 = ch / 9, k2 = ch - c32 * 9;
        int t = (b * K2 + k2) * NPIX + p0 + pl_b;
        int4   o  = __ldg(&g_sidx[t]);
        float4 wt = __ldg(&g_swt[t]);
        int cio = c32 * 4 + ksg_b;               // uint4 offset within pixel row
        uint4 u00 = __ldg(&Xh[o.x + cio]);
        uint4 u01 = __ldg(&Xh[o.y + cio]);
        uint4 u10 = __ldg(&Xh[o.z + cio]);
        uint4 u11 = __ldg(&Xh[o.w + cio]);
        float fa[8], fb[8], fc[8], fd[8];
        h8_to_f(u00, fa); h8_to_f(u01, fb); h8_to_f(u10, fc); h8_to_f(u11, fd);
        float v[8];
#pragma unroll
        for (int k = 0; k < 8; k++)
            v[k] = wt.x * fa[k] + wt.y * fb[k] + wt.z * fc[k] + wt.w * fd[k];
        // permuted order: pos <- k pairs (0,4),(1,5),(2,6),(3,7)
        uint4 s1 = make_uint4(f2tf32(v[0]), f2tf32(v[4]), f2tf32(v[1]), f2tf32(v[5]));
        uint4 s2 = make_uint4(f2tf32(v[2]), f2tf32(v[6]), f2tf32(v[3]), f2tf32(v[7]));
        uint4* ab = (uint4*)(A_s[s] + pl_b * SROW + ksg_b * 8);
        ab[0] = s1;
        ab[1] = s2;
    };

    // ---- prologue: build chunk 0 ----
    build_W(0, 0);
    build_A(0, 0);
    asm volatile("cp.async.wait_group 0;" ::: "memory");
    __syncthreads();

    for (int ch = 0; ch < NCHUNK; ch++) {
        int s = ch & 1;
        if (ch + 1 < NCHUNK) build_W(ch + 1, s ^ 1);

        // ---- mma on buffer s: all fragment loads are LDS.64 ----
        const float* As = A_s[s] + (wm * 32 + ty) * SROW + 2 * tk;
        const float* Ws = W_s[s] + (wn * 64 + ty) * SROW + 2 * tk;
#pragma unroll
        for (int ks = 0; ks < 4; ks++) {
            float2 al[2], ah[2], bv[8];
#pragma unroll
            for (int i = 0; i < 2; i++) {
                al[i] = *(const float2*)(As + i * (16 * SROW) + ks * 8);
                ah[i] = *(const float2*)(As + i * (16 * SROW) + 8 * SROW + ks * 8);
            }
#pragma unroll
            for (int j = 0; j < 8; j++)
                bv[j] = *(const float2*)(Ws + j * (8 * SROW) + ks * 8);
#pragma unroll
            for (int i = 0; i < 2; i++) {
                uint32_t a[4] = { __float_as_uint(al[i].x), __float_as_uint(ah[i].x),
                                  __float_as_uint(al[i].y), __float_as_uint(ah[i].y) };
#pragma unroll
                for (int j = 0; j < 8; j++) {
                    uint32_t bb[2] = { __float_as_uint(bv[j].x), __float_as_uint(bv[j].y) };
                    mma_tf32(acc[i][j], a, bb);
                }
            }
        }

        if (ch + 1 < NCHUNK) build_A(ch + 1, s ^ 1);
        asm volatile("cp.async.wait_group 0;" ::: "memory");
        __syncthreads();
    }

    // ---- epilogue: bias + store NCHW ----
    float* ob = out + (size_t)b * COUT * NPIX;
#pragma unroll
    for (int j = 0; j < 8; j++) {
        int co = wn * 64 + j * 8 + 2 * tk;
        float b0 = sB[co], b1 = sB[co + 1];
#pragma unroll
        for (int i = 0; i < 2; i++) {
            int px = p0 + wm * 32 + i * 16 + ty;
            ob[(size_t)co * NPIX + px]           = acc[i][j][0] + b0;
            ob[(size_t)(co + 1) * NPIX + px]     = acc[i][j][1] + b1;
            ob[(size_t)co * NPIX + px + 8]       = acc[i][j][2] + b0;
            ob[(size_t)(co + 1) * NPIX + px + 8] = acc[i][j][3] + b1;
        }
    }
}

// ---------------------------------------------------------------------------
// GroupNorm(32) + ReLU in place
__global__ __launch_bounds__(256)
void k_gn(float* __restrict__ out,
          const float* __restrict__ gamma, const float* __restrict__ beta) {
    int b = blockIdx.x >> 5;
    int g = blockIdx.x & 31;
    float4* b4 = (float4*)(out + ((size_t)(b * COUT + g * 8)) * NPIX);
    int tid = threadIdx.x;

    float s = 0.f, ss = 0.f;
    for (int i = tid; i < 8192; i += 256) {
        float4 v = b4[i];
        s  += v.x + v.y + v.z + v.w;
        ss += v.x * v.x + v.y * v.y + v.z * v.z + v.w * v.w;
    }
#pragma unroll
    for (int o = 16; o; o >>= 1) {
        s  += __shfl_down_sync(0xFFFFFFFFu, s, o);
        ss += __shfl_down_sync(0xFFFFFFFFu, ss, o);
    }
    __shared__ float red[16];
    __shared__ float stats[2];
    int warp = tid >> 5, lane = tid & 31;
    if (lane == 0) { red[warp] = s; red[warp + 8] = ss; }
    __syncthreads();
    if (tid == 0) {
        float S = 0.f, SS = 0.f;
#pragma unroll
        for (int i = 0; i < 8; i++) { S += red[i]; SS += red[i + 8]; }
        float mu  = S * (1.f / 32768.f);
        float var = SS * (1.f / 32768.f) - mu * mu;
        stats[0] = mu;
        stats[1] = rsqrtf(var + 1e-5f);
    }
    __syncthreads();
    float mu = stats[0], rstd = stats[1];
    for (int i = tid; i < 8192; i += 256) {
        int c = g * 8 + (i >> 10);
        float ga = gamma[c], be = beta[c];
        float4 v = b4[i];
        v.x = fmaxf((v.x - mu) * rstd * ga + be, 0.f);
        v.y = fmaxf((v.y - mu) * rstd * ga + be, 0.f);
        v.z = fmaxf((v.z - mu) * rstd * ga + be, 0.f);
        v.w = fmaxf((v.w - mu) * rstd * ga + be, 0.f);
        b4[i] = v;
    }
}

// ---------------------------------------------------------------------------
extern "C" void kernel_launch(void* const* d_in, const int* in_sizes, int n_in,
                              void* d_out, int out_size) {
    const float* x      = (const float*)d_in[0];
    const float* offset = (const float*)d_in[1];
    const float* mask   = (const float*)d_in[2];
    const float* weight = (const float*)d_in[3];
    const float* bias   = (const float*)d_in[4];
    const float* gamma  = (const float*)d_in[5];
    const float* beta   = (const float*)d_in[6];
    float* out = (float*)d_out;

    cudaFuncSetAttribute(k_conv, cudaFuncAttributeMaxDynamicSharedMemorySize, SMEM_DYN);

    k_prep_x<<<dim3(128, 8, 4), dim3(32, 8)>>>(x);
    k_prep_w<<<NCHUNK, 256>>>(weight);
    k_prep_params<<<576, 256>>>(offset, mask);
    k_conv<<<256, 256, SMEM_DYN>>>(bias, out);
    k_gn<<<128, 256>>>(out, gamma, beta);
}

// round 7
// speedup vs baseline: 1.5967x; 1.5967x over previous
#include <cuda_runtime.h>
#include <cuda_fp16.h>
#include <cstdint>

#define B_    4
#define CIN   256
#define HH    64
#define WW    64
#define COUT  256
#define K2    9
#define NPIX  4096
#define NCHUNK 36               // 4 ci64-chunks * 9 k2, order: c64 outer, k2 inner
#define RPITCH 160              // bytes per smem row (64 halves data + pad): conflict-free LDS.64

// ---------------- scratch ----------------
__device__ __align__(16) __half   g_xh[B_ * NPIX * CIN];     // x NHWC fp16
__device__ __align__(16) __half   g_wh[NCHUNK * 256 * 64];   // W fp16: [ch][co256][k64 permuted]
__device__ __align__(16) int4     g_sidx[B_ * K2 * NPIX];    // corner bases in uint4 units (pix*32)
__device__ __align__(16) float4   g_swt [B_ * K2 * NPIX];

__device__ __forceinline__ uint32_t smem_u32(const void* p) {
    uint32_t a;
    asm("{ .reg .u64 t; cvta.to.shared.u64 t, %1; cvt.u32.u64 %0, t; }" : "=r"(a) : "l"(p));
    return a;
}
__device__ __forceinline__ void mma_f16(float* c, uint32_t a0, uint32_t a1,
                                        uint32_t a2, uint32_t a3,
                                        uint32_t b0, uint32_t b1) {
    asm volatile("mma.sync.aligned.m16n8k16.row.col.f32.f16.f16.f32 "
        "{%0,%1,%2,%3}, {%4,%5,%6,%7}, {%8,%9}, {%0,%1,%2,%3};"
        : "+f"(c[0]), "+f"(c[1]), "+f"(c[2]), "+f"(c[3])
        : "r"(a0), "r"(a1), "r"(a2), "r"(a3), "r"(b0), "r"(b1));
}
__device__ __forceinline__ void h8_to_f(uint4 u, float* f) {
    const __half2* h = (const __half2*)&u;
#pragma unroll
    for (int i = 0; i < 4; i++) {
        float2 t = __half22float2(h[i]);
        f[2 * i] = t.x;
        f[2 * i + 1] = t.y;
    }
}
__device__ __forceinline__ uint32_t pack2(float a, float b) {
    __half2 h = __floats2half2_rn(a, b);
    return *(uint32_t*)&h;
}

// ---------------------------------------------------------------------------
// Prep 1: x NCHW -> NHWC fp16
__global__ void k_prep_x(const float* __restrict__ x) {
    __shared__ float tile[32][33];
    int b = blockIdx.z, p0 = blockIdx.x * 32, c0 = blockIdx.y * 32;
    int tx = threadIdx.x, ty = threadIdx.y;
#pragma unroll
    for (int i = ty; i < 32; i += 8)
        tile[i][tx] = x[(b * CIN + c0 + i) * NPIX + p0 + tx];
    __syncthreads();
#pragma unroll
    for (int i = ty; i < 32; i += 8)
        g_xh[(b * NPIX + p0 + i) * CIN + c0 + tx] = __float2half_rn(tile[tx][i]);
}

// Prep 2: W -> fp16 chunks [ch = c64*9 + k2][co][k64], k permuted within each
// group of 16: pos 4t+{0,1,2,3} <- k {2t, 2t+1, 2t+8, 2t+9}. The A tile uses
// the identical permutation, so the GEMM is unchanged while each m16n8k16
// fragment becomes a single LDS.64.
__global__ void k_prep_w(const float* __restrict__ w) {
    int ch  = blockIdx.x;
    int c64 = ch / 9, k2 = ch - c64 * 9;
    __half* dst = g_wh + ch * 16384;
    for (int e = threadIdx.x; e < 16384; e += 256) {
        int co = e >> 6, p = e & 63;
        int gp = p >> 4, r = p & 15, t = r >> 2, u = r & 3;
        int k = gp * 16 + 2 * t + (u & 1) + ((u & 2) ? 8 : 0);
        float v = w[(co * CIN + c64 * 64 + k) * K2 + k2];
        dst[co * 64 + p] = __float2half_rn(v);
    }
}

// Prep 3: sampling params (corner bases in uint4 units, folded weights)
__global__ void k_prep_params(const float* __restrict__ offset,
                              const float* __restrict__ mask) {
    int t = blockIdx.x * blockDim.x + threadIdx.x;
    int b  = t / (K2 * NPIX);
    int r  = t - b * (K2 * NPIX);
    int k2 = r >> 12;
    int p  = r & (NPIX - 1);
    int ho = p >> 6, wo = p & 63;
    int ky = k2 / 3, kx = k2 - ky * 3;

    float dy_off = offset[(b * 2 * K2 + 2 * k2    ) * NPIX + p];
    float dx_off = offset[(b * 2 * K2 + 2 * k2 + 1) * NPIX + p];
    float m      = mask  [(b * K2 + k2) * NPIX + p];

    float yf = (float)(ky + ho - 1) + dy_off;
    float xf = (float)(kx + wo - 1) + dx_off;
    float y0f = floorf(yf), x0f = floorf(xf);
    float dy = yf - y0f, dx = xf - x0f;
    int y0 = (int)y0f, x0 = (int)x0f;
    int y1 = y0 + 1,   x1 = x0 + 1;

    float w00 = (1.f - dy) * (1.f - dx) * m;
    float w01 = (1.f - dy) * dx * m;
    float w10 = dy * (1.f - dx) * m;
    float w11 = dy * dx * m;
    bool vy0 = (y0 >= 0) & (y0 < HH), vy1 = (y1 >= 0) & (y1 < HH);
    bool vx0 = (x0 >= 0) & (x0 < WW), vx1 = (x1 >= 0) & (x1 < WW);
    if (!(vy0 & vx0)) w00 = 0.f;
    if (!(vy0 & vx1)) w01 = 0.f;
    if (!(vy1 & vx0)) w10 = 0.f;
    if (!(vy1 & vx1)) w11 = 0.f;

    int y0c = min(max(y0, 0), HH - 1), y1c = min(max(y1, 0), HH - 1);
    int x0c = min(max(x0, 0), WW - 1), x1c = min(max(x1, 0), WW - 1);
    int base = b * NPIX;
    g_sidx[t] = make_int4((base + y0c * WW + x0c) * 32,
                          (base + y0c * WW + x1c) * 32,
                          (base + y1c * WW + x0c) * 32,
                          (base + y1c * WW + x1c) * 32);
    g_swt[t] = make_float4(w00, w01, w10, w11);
}

// ---------------------------------------------------------------------------
// Main: fp16 m16n8k16 implicit GEMM, fp32 accumulate.
// CTA: 64px x 256co, K=2304 in 36 chunks of 64 (c64 outer, k2 inner).
// grid 256, block 256 (8 warps), warp tile 32px x 64co, 2 CTAs/SM.
// Double-buffered A(2x10KB fp16)/W(2x40KB fp16), permuted-k, LDS.64 frags.
// ---------------------------------------------------------------------------
// bytes: A0 0 | A1 10240 | W0 20480 | W1 61440 | sB 102400 | end 103424
#define SMEM_DYN 103424

__global__ __launch_bounds__(256, 2)
void k_conv(const float* __restrict__ bias, float* __restrict__ out) {
    extern __shared__ char dsm[];
    char*  A_s[2] = { dsm,         dsm + 10240 };
    char*  W_s[2] = { dsm + 20480, dsm + 61440 };
    float* sB = (float*)(dsm + 102400);

    int tid  = threadIdx.x;
    int b    = blockIdx.x >> 6;
    int p0   = (blockIdx.x & 63) * 64;
    int warp = tid >> 5, lane = tid & 31;

    sB[tid] = bias[tid];

    // ---- per-thread mappings ----
    int ty = lane >> 2, tk = lane & 3;        // mma frag coords
    int wm = warp >> 2, wn = warp & 3;        // warp tile: px wm*32, co wn*64
    int pl_b = tid >> 2, q_b = tid & 3;       // A-build: pixel, k-group-of-16
    const uint4* Xh = (const uint4*)g_xh;

    float acc[2][8][4];
#pragma unroll
    for (int i = 0; i < 2; i++)
#pragma unroll
        for (int j = 0; j < 8; j++)
#pragma unroll
            for (int qq = 0; qq < 4; qq++) acc[i][j][qq] = 0.f;

    // ---- builders ----
    auto build_W = [&](int ch, int s) {
        const char* src = (const char*)(g_wh + ch * 16384);
        uint32_t dst = smem_u32(W_s[s]);
#pragma unroll
        for (int i = 0; i < 8; i++) {
            int lin = tid + i * 256;             // 0..2047
            int co = lin >> 3, seg = lin & 7;    // 16B segment of 128B row
            uint32_t d = dst + (uint32_t)(co * RPITCH + seg * 16);
            const char* gp = src + (size_t)lin * 16;
            asm volatile("cp.async.cg.shared.global [%0], [%1], 16;" :: "r"(d), "l"(gp));
        }
        asm volatile("cp.async.commit_group;" ::: "memory");
    };
    auto build_A = [&](int ch, int s) {
        int c64 = ch / 9, k2 = ch - c64 * 9;
        int t = (b * K2 + k2) * NPIX + p0 + pl_b;
        int4   o  = __ldg(&g_sidx[t]);
        float4 wt = __ldg(&g_swt[t]);
        int cio = c64 * 8 + 2 * q_b;             // uint4 offset within pixel row
        float fa[16], fb[16], fc[16], fd[16];
        h8_to_f(__ldg(&Xh[o.x + cio]), fa); h8_to_f(__ldg(&Xh[o.x + cio + 1]), fa + 8);
        h8_to_f(__ldg(&Xh[o.y + cio]), fb); h8_to_f(__ldg(&Xh[o.y + cio + 1]), fb + 8);
        h8_to_f(__ldg(&Xh[o.z + cio]), fc); h8_to_f(__ldg(&Xh[o.z + cio + 1]), fc + 8);
        h8_to_f(__ldg(&Xh[o.w + cio]), fd); h8_to_f(__ldg(&Xh[o.w + cio + 1]), fd + 8);
        float v[16];
#pragma unroll
        for (int k = 0; k < 16; k++)
            v[k] = wt.x * fa[k] + wt.y * fb[k] + wt.z * fc[k] + wt.w * fd[k];
        // permuted pack: pos 4t+{0..3} <- v[2t], v[2t+1], v[2t+8], v[2t+9]
        uint4 s1 = make_uint4(pack2(v[0], v[1]), pack2(v[8],  v[9]),
                              pack2(v[2], v[3]), pack2(v[10], v[11]));
        uint4 s2 = make_uint4(pack2(v[4], v[5]), pack2(v[12], v[13]),
                              pack2(v[6], v[7]), pack2(v[14], v[15]));
        uint4* ab = (uint4*)(A_s[s] + pl_b * RPITCH + q_b * 32);
        ab[0] = s1;
        ab[1] = s2;
    };

    // ---- prologue: build chunk 0 ----
    build_W(0, 0);
    build_A(0, 0);
    asm volatile("cp.async.wait_group 0;" ::: "memory");
    __syncthreads();

    for (int ch = 0; ch < NCHUNK; ch++) {
        int s = ch & 1;
        if (ch + 1 < NCHUNK) build_W(ch + 1, s ^ 1);

        // ---- mma on buffer s: every fragment is one LDS.64 ----
        const char* As = A_s[s] + (wm * 32 + ty) * RPITCH + tk * 8;
        const char* Ws = W_s[s] + (wn * 64 + ty) * RPITCH + tk * 8;
#pragma unroll
        for (int ks = 0; ks < 4; ks++) {
            uint2 alo[2], ahi[2], bv[8];
#pragma unroll
            for (int i = 0; i < 2; i++) {
                alo[i] = *(const uint2*)(As + i * (16 * RPITCH) + ks * 32);
                ahi[i] = *(const uint2*)(As + i * (16 * RPITCH) + 8 * RPITCH + ks * 32);
            }
#pragma unroll
            for (int j = 0; j < 8; j++)
                bv[j] = *(const uint2*)(Ws + j * (8 * RPITCH) + ks * 32);
#pragma unroll
            for (int i = 0; i < 2; i++)
#pragma unroll
                for (int j = 0; j < 8; j++)
                    mma_f16(acc[i][j], alo[i].x, ahi[i].x, alo[i].y, ahi[i].y,
                            bv[j].x, bv[j].y);
        }

        if (ch + 1 < NCHUNK) build_A(ch + 1, s ^ 1);
        asm volatile("cp.async.wait_group 0;" ::: "memory");
        __syncthreads();
    }

    // ---- epilogue: bias + store NCHW ----
    float* ob = out + (size_t)b * COUT * NPIX;
#pragma unroll
    for (int j = 0; j < 8; j++) {
        int co = wn * 64 + j * 8 + 2 * tk;
        float b0 = sB[co], b1 = sB[co + 1];
#pragma unroll
        for (int i = 0; i < 2; i++) {
            int px = p0 + wm * 32 + i * 16 + ty;
            ob[(size_t)co * NPIX + px]           = acc[i][j][0] + b0;
            ob[(size_t)(co + 1) * NPIX + px]     = acc[i][j][1] + b1;
            ob[(size_t)co * NPIX + px + 8]       = acc[i][j][2] + b0;
            ob[(size_t)(co + 1) * NPIX + px + 8] = acc[i][j][3] + b1;
        }
    }
}

// ---------------------------------------------------------------------------
// GroupNorm(32) + ReLU in place
__global__ __launch_bounds__(256)
void k_gn(float* __restrict__ out,
          const float* __restrict__ gamma, const float* __restrict__ beta) {
    int b = blockIdx.x >> 5;
    int g = blockIdx.x & 31;
    float4* b4 = (float4*)(out + ((size_t)(b * COUT + g * 8)) * NPIX);
    int tid = threadIdx.x;

    float s = 0.f, ss = 0.f;
    for (int i = tid; i < 8192; i += 256) {
        float4 v = b4[i];
        s  += v.x + v.y + v.z + v.w;
        ss += v.x * v.x + v.y * v.y + v.z * v.z + v.w * v.w;
    }
#pragma unroll
    for (int o = 16; o; o >>= 1) {
        s  += __shfl_down_sync(0xFFFFFFFFu, s, o);
        ss += __shfl_down_sync(0xFFFFFFFFu, ss, o);
    }
    __shared__ float red[16];
    __shared__ float stats[2];
    int warp = tid >> 5, lane = tid & 31;
    if (lane == 0) { red[warp] = s; red[warp + 8] = ss; }
    __syncthreads();
    if (tid == 0) {
        float S = 0.f, SS = 0.f;
#pragma unroll
        for (int i = 0; i < 8; i++) { S += red[i]; SS += red[i + 8]; }
        float mu  = S * (1.f / 32768.f);
        float var = SS * (1.f / 32768.f) - mu * mu;
        stats[0] = mu;
        stats[1] = rsqrtf(var + 1e-5f);
    }
    __syncthreads();
    float mu = stats[0], rstd = stats[1];
    for (int i = tid; i < 8192; i += 256) {
        int c = g * 8 + (i >> 10);
        float ga = gamma[c], be = beta[c];
        float4 v = b4[i];
        v.x = fmaxf((v.x - mu) * rstd * ga + be, 0.f);
        v.y = fmaxf((v.y - mu) * rstd * ga + be, 0.f);
        v.z = fmaxf((v.z - mu) * rstd * ga + be, 0.f);
        v.w = fmaxf((v.w - mu) * rstd * ga + be, 0.f);
        b4[i] = v;
    }
}

// ---------------------------------------------------------------------------
extern "C" void kernel_launch(void* const* d_in, const int* in_sizes, int n_in,
                              void* d_out, int out_size) {
    const float* x      = (const float*)d_in[0];
    const float* offset = (const float*)d_in[1];
    const float* mask   = (const float*)d_in[2];
    const float* weight = (const float*)d_in[3];
    const float* bias   = (const float*)d_in[4];
    const float* gamma  = (const float*)d_in[5];
    const float* beta   = (const float*)d_in[6];
    float* out = (float*)d_out;

    cudaFuncSetAttribute(k_conv, cudaFuncAttributeMaxDynamicSharedMemorySize, SMEM_DYN);

    k_prep_x<<<dim3(128, 8, 4), dim3(32, 8)>>>(x);
    k_prep_w<<<NCHUNK, 256>>>(weight);
    k_prep_params<<<576, 256>>>(offset, mask);
    k_conv<<<256, 256, SMEM_DYN>>>(bias, out);
    k_gn<<<128, 256>>>(out, gamma, beta);
}

// round 8
// speedup vs baseline: 1.6835x; 1.0544x over previous
#include <cuda_runtime.h>
#include <cuda_fp16.h>
#include <cstdint>

#define B_    4
#define CIN   256
#define HH    64
#define WW    64
#define COUT  256
#define K2    9
#define NPIX  4096
#define NCHUNK 36               // 4 ci64-chunks * 9 k2, order: c64 outer, k2 inner
#define RPITCH 160              // bytes per smem row (64 halves data + pad): conflict-free LDS.64

// ---------------- scratch ----------------
__device__ __align__(16) __half   g_xh[B_ * NPIX * CIN];     // x NHWC fp16
__device__ __align__(16) __half   g_wh[NCHUNK * 256 * 64];   // W fp16: [ch][co256][k64 permuted]
__device__ __align__(16) int4     g_sidx[B_ * K2 * NPIX];    // corner bases in uint4 units (pix*32)
__device__ __align__(16) float4   g_swt [B_ * K2 * NPIX];
__device__ __align__(16) float2   g_part[B_ * 32 * 64];      // GN partials [(b*32+g)*64 + tile]

__device__ __forceinline__ uint32_t smem_u32(const void* p) {
    uint32_t a;
    asm("{ .reg .u64 t; cvta.to.shared.u64 t, %1; cvt.u32.u64 %0, t; }" : "=r"(a) : "l"(p));
    return a;
}
__device__ __forceinline__ void mma_f16(float* c, uint32_t a0, uint32_t a1,
                                        uint32_t a2, uint32_t a3,
                                        uint32_t b0, uint32_t b1) {
    asm volatile("mma.sync.aligned.m16n8k16.row.col.f32.f16.f16.f32 "
        "{%0,%1,%2,%3}, {%4,%5,%6,%7}, {%8,%9}, {%0,%1,%2,%3};"
        : "+f"(c[0]), "+f"(c[1]), "+f"(c[2]), "+f"(c[3])
        : "r"(a0), "r"(a1), "r"(a2), "r"(a3), "r"(b0), "r"(b1));
}

// ---------------------------------------------------------------------------
// Prep 1: x NCHW -> NHWC fp16
__global__ void k_prep_x(const float* __restrict__ x) {
    __shared__ float tile[32][33];
    int b = blockIdx.z, p0 = blockIdx.x * 32, c0 = blockIdx.y * 32;
    int tx = threadIdx.x, ty = threadIdx.y;
#pragma unroll
    for (int i = ty; i < 32; i += 8)
        tile[i][tx] = x[(b * CIN + c0 + i) * NPIX + p0 + tx];
    __syncthreads();
#pragma unroll
    for (int i = ty; i < 32; i += 8)
        g_xh[(b * NPIX + p0 + i) * CIN + c0 + tx] = __float2half_rn(tile[tx][i]);
}

// Prep 2: W -> fp16 chunks [ch = c64*9 + k2][co][k64], k permuted within each
// group of 16: pos 4t+{0,1,2,3} <- k {2t, 2t+1, 2t+8, 2t+9}. A uses the same
// permutation, so the GEMM is unchanged while each fragment is one LDS.64.
__global__ void k_prep_w(const float* __restrict__ w) {
    int ch  = blockIdx.x;
    int c64 = ch / 9, k2 = ch - c64 * 9;
    __half* dst = g_wh + ch * 16384;
    for (int e = threadIdx.x; e < 16384; e += 256) {
        int co = e >> 6, p = e & 63;
        int gp = p >> 4, r = p & 15, t = r >> 2, u = r & 3;
        int k = gp * 16 + 2 * t + (u & 1) + ((u & 2) ? 8 : 0);
        float v = w[(co * CIN + c64 * 64 + k) * K2 + k2];
        dst[co * 64 + p] = __float2half_rn(v);
    }
}

// Prep 3: sampling params (corner bases in uint4 units, folded weights)
__global__ void k_prep_params(const float* __restrict__ offset,
                              const float* __restrict__ mask) {
    int t = blockIdx.x * blockDim.x + threadIdx.x;
    int b  = t / (K2 * NPIX);
    int r  = t - b * (K2 * NPIX);
    int k2 = r >> 12;
    int p  = r & (NPIX - 1);
    int ho = p >> 6, wo = p & 63;
    int ky = k2 / 3, kx = k2 - ky * 3;

    float dy_off = offset[(b * 2 * K2 + 2 * k2    ) * NPIX + p];
    float dx_off = offset[(b * 2 * K2 + 2 * k2 + 1) * NPIX + p];
    float m      = mask  [(b * K2 + k2) * NPIX + p];

    float yf = (float)(ky + ho - 1) + dy_off;
    float xf = (float)(kx + wo - 1) + dx_off;
    float y0f = floorf(yf), x0f = floorf(xf);
    float dy = yf - y0f, dx = xf - x0f;
    int y0 = (int)y0f, x0 = (int)x0f;
    int y1 = y0 + 1,   x1 = x0 + 1;

    float w00 = (1.f - dy) * (1.f - dx) * m;
    float w01 = (1.f - dy) * dx * m;
    float w10 = dy * (1.f - dx) * m;
    float w11 = dy * dx * m;
    bool vy0 = (y0 >= 0) & (y0 < HH), vy1 = (y1 >= 0) & (y1 < HH);
    bool vx0 = (x0 >= 0) & (x0 < WW), vx1 = (x1 >= 0) & (x1 < WW);
    if (!(vy0 & vx0)) w00 = 0.f;
    if (!(vy0 & vx1)) w01 = 0.f;
    if (!(vy1 & vx0)) w10 = 0.f;
    if (!(vy1 & vx1)) w11 = 0.f;

    int y0c = min(max(y0, 0), HH - 1), y1c = min(max(y1, 0), HH - 1);
    int x0c = min(max(x0, 0), WW - 1), x1c = min(max(x1, 0), WW - 1);
    int base = b * NPIX;
    g_sidx[t] = make_int4((base + y0c * WW + x0c) * 32,
                          (base + y0c * WW + x1c) * 32,
                          (base + y1c * WW + x0c) * 32,
                          (base + y1c * WW + x1c) * 32);
    g_swt[t] = make_float4(w00, w01, w10, w11);
}

// ---------------------------------------------------------------------------
// Main: fp16 m16n8k16 implicit GEMM, fp32 accumulate + fused GN partial stats.
// CTA: 64px x 256co, K=2304 in 36 chunks of 64 (c64 outer, k2 inner).
// grid 256, block 256 (8 warps), warp tile 32px x 64co, 2 CTAs/SM.
// build_A bilinear fully in half2 (4 HFMA2 per 2 channels).
// ---------------------------------------------------------------------------
// bytes: A0 0 | A1 10240 | W0 20480 | W1 61440 | sB 102400 | sP 103424 | end 103936
#define SMEM_DYN 103936

__global__ __launch_bounds__(256, 2)
void k_conv(const float* __restrict__ bias, float* __restrict__ out) {
    extern __shared__ char dsm[];
    char*   A_s[2] = { dsm,         dsm + 10240 };
    char*   W_s[2] = { dsm + 20480, dsm + 61440 };
    float*  sB = (float*)(dsm + 102400);
    float2* sP = (float2*)(dsm + 103424);        // [2 wm][32 groups]

    int tid  = threadIdx.x;
    int b    = blockIdx.x >> 6;
    int tile = blockIdx.x & 63;
    int p0   = tile * 64;
    int warp = tid >> 5, lane = tid & 31;

    sB[tid] = bias[tid];

    // ---- per-thread mappings ----
    int ty = lane >> 2, tk = lane & 3;        // mma frag coords
    int wm = warp >> 2, wn = warp & 3;        // warp tile: px wm*32, co wn*64
    int pl_b = tid >> 2, q_b = tid & 3;       // A-build: pixel, k-group-of-16
    const uint4* Xh = (const uint4*)g_xh;

    float acc[2][8][4];
#pragma unroll
    for (int i = 0; i < 2; i++)
#pragma unroll
        for (int j = 0; j < 8; j++)
#pragma unroll
            for (int qq = 0; qq < 4; qq++) acc[i][j][qq] = 0.f;

    // ---- builders ----
    auto build_W = [&](int ch, int s) {
        const char* src = (const char*)(g_wh + ch * 16384);
        uint32_t dst = smem_u32(W_s[s]);
#pragma unroll
        for (int i = 0; i < 8; i++) {
            int lin = tid + i * 256;             // 0..2047
            int co = lin >> 3, seg = lin & 7;    // 16B segment of 128B row
            uint32_t d = dst + (uint32_t)(co * RPITCH + seg * 16);
            const char* gp = src + (size_t)lin * 16;
            asm volatile("cp.async.cg.shared.global [%0], [%1], 16;" :: "r"(d), "l"(gp));
        }
        asm volatile("cp.async.commit_group;" ::: "memory");
    };
    auto build_A = [&](int ch, int s) {
        int c64 = ch / 9, k2 = ch - c64 * 9;
        int t = (b * K2 + k2) * NPIX + p0 + pl_b;
        int4   o  = __ldg(&g_sidx[t]);
        float4 wt = __ldg(&g_swt[t]);
        int cio = c64 * 8 + 2 * q_b;             // uint4 offset within pixel row
        uint4 ua0 = __ldg(&Xh[o.x + cio]), ua1 = __ldg(&Xh[o.x + cio + 1]);
        uint4 ub0 = __ldg(&Xh[o.y + cio]), ub1 = __ldg(&Xh[o.y + cio + 1]);
        uint4 uc0 = __ldg(&Xh[o.z + cio]), uc1 = __ldg(&Xh[o.z + cio + 1]);
        uint4 ud0 = __ldg(&Xh[o.w + cio]), ud1 = __ldg(&Xh[o.w + cio + 1]);
        __half2 w00 = __float2half2_rn(wt.x);
        __half2 w01 = __float2half2_rn(wt.y);
        __half2 w10 = __float2half2_rn(wt.z);
        __half2 w11 = __float2half2_rn(wt.w);
        const __half2* A2 = (const __half2*)&ua0;   // ua0,ua1 contiguous on stack?
        __half2 va[8], vb[8], vc[8], vd[8];
        *(uint4*)&va[0] = ua0; *(uint4*)&va[4] = ua1;
        *(uint4*)&vb[0] = ub0; *(uint4*)&vb[4] = ub1;
        *(uint4*)&vc[0] = uc0; *(uint4*)&vc[4] = uc1;
        *(uint4*)&vd[0] = ud0; *(uint4*)&vd[4] = ud1;
        (void)A2;
        __half2 v[8];
#pragma unroll
        for (int h = 0; h < 8; h++) {
            __half2 r = __hmul2(w00, va[h]);
            r = __hfma2(w01, vb[h], r);
            r = __hfma2(w10, vc[h], r);
            v[h] = __hfma2(w11, vd[h], r);
        }
        // permuted pack (half2 slots): out[2t]=v[t], out[2t+1]=v[t+4]
        uint32_t* vv = (uint32_t*)v;
        uint4 s1 = make_uint4(vv[0], vv[4], vv[1], vv[5]);
        uint4 s2 = make_uint4(vv[2], vv[6], vv[3], vv[7]);
        uint4* ab = (uint4*)(A_s[s] + pl_b * RPITCH + q_b * 32);
        ab[0] = s1;
        ab[1] = s2;
    };

    // ---- prologue: build chunk 0 ----
    build_W(0, 0);
    build_A(0, 0);
    asm volatile("cp.async.wait_group 0;" ::: "memory");
    __syncthreads();

    for (int ch = 0; ch < NCHUNK; ch++) {
        int s = ch & 1;
        if (ch + 1 < NCHUNK) build_W(ch + 1, s ^ 1);

        // ---- mma on buffer s: every fragment is one LDS.64 ----
        const char* As = A_s[s] + (wm * 32 + ty) * RPITCH + tk * 8;
        const char* Ws = W_s[s] + (wn * 64 + ty) * RPITCH + tk * 8;
#pragma unroll
        for (int ks = 0; ks < 4; ks++) {
            uint2 alo[2], ahi[2], bv[8];
#pragma unroll
            for (int i = 0; i < 2; i++) {
                alo[i] = *(const uint2*)(As + i * (16 * RPITCH) + ks * 32);
                ahi[i] = *(const uint2*)(As + i * (16 * RPITCH) + 8 * RPITCH + ks * 32);
            }
#pragma unroll
            for (int j = 0; j < 8; j++)
                bv[j] = *(const uint2*)(Ws + j * (8 * RPITCH) + ks * 32);
#pragma unroll
            for (int i = 0; i < 2; i++)
#pragma unroll
                for (int j = 0; j < 8; j++)
                    mma_f16(acc[i][j], alo[i].x, ahi[i].x, alo[i].y, ahi[i].y,
                            bv[j].x, bv[j].y);
        }

        if (ch + 1 < NCHUNK) build_A(ch + 1, s ^ 1);
        asm volatile("cp.async.wait_group 0;" ::: "memory");
        __syncthreads();
    }

    // ---- epilogue: bias + store NCHW + per-group GN partial sums ----
    float* ob = out + (size_t)b * COUT * NPIX;
#pragma unroll
    for (int j = 0; j < 8; j++) {
        int co = wn * 64 + j * 8 + 2 * tk;
        float b0 = sB[co], b1 = sB[co + 1];
        float s = 0.f, ss = 0.f;
#pragma unroll
        for (int i = 0; i < 2; i++) {
            int px = p0 + wm * 32 + i * 16 + ty;
            float v0 = acc[i][j][0] + b0;
            float v1 = acc[i][j][1] + b1;
            float v2 = acc[i][j][2] + b0;
            float v3 = acc[i][j][3] + b1;
            ob[(size_t)co * NPIX + px]           = v0;
            ob[(size_t)(co + 1) * NPIX + px]     = v1;
            ob[(size_t)co * NPIX + px + 8]       = v2;
            ob[(size_t)(co + 1) * NPIX + px + 8] = v3;
            s  += v0 + v1 + v2 + v3;
            ss += v0 * v0 + v1 * v1 + v2 * v2 + v3 * v3;
        }
#pragma unroll
        for (int o = 16; o; o >>= 1) {
            s  += __shfl_down_sync(0xFFFFFFFFu, s, o);
            ss += __shfl_down_sync(0xFFFFFFFFu, ss, o);
        }
        if (lane == 0) sP[wm * 32 + wn * 8 + j] = make_float2(s, ss);
    }
    __syncthreads();
    if (tid < 32) {
        float2 q0 = sP[tid], q1 = sP[32 + tid];
        g_part[(b * 32 + tid) * 64 + tile] = make_float2(q0.x + q1.x, q0.y + q1.y);
    }
}

// ---------------------------------------------------------------------------
// GroupNorm(32) + ReLU: stats from precomputed partials, one normalize pass.
__global__ __launch_bounds__(256)
void k_gn(float* __restrict__ out,
          const float* __restrict__ gamma, const float* __restrict__ beta) {
    int b = blockIdx.x >> 5;
    int g = blockIdx.x & 31;
    int tid = threadIdx.x;
    __shared__ float2 sp[64];
    __shared__ float stats[2];
    if (tid < 64) sp[tid] = g_part[(b * 32 + g) * 64 + tid];
    __syncthreads();
    if (tid == 0) {
        float S = 0.f, SS = 0.f;
#pragma unroll
        for (int i = 0; i < 64; i++) { S += sp[i].x; SS += sp[i].y; }
        float mu  = S * (1.f / 32768.f);
        float var = SS * (1.f / 32768.f) - mu * mu;
        stats[0] = mu;
        stats[1] = rsqrtf(var + 1e-5f);
    }
    __syncthreads();
    float mu = stats[0], rstd = stats[1];
    float4* b4 = (float4*)(out + ((size_t)(b * COUT + g * 8)) * NPIX);
    for (int i = tid; i < 8192; i += 256) {
        int c = g * 8 + (i >> 10);
        float ga = gamma[c], be = beta[c];
        float4 v = b4[i];
        v.x = fmaxf((v.x - mu) * rstd * ga + be, 0.f);
        v.y = fmaxf((v.y - mu) * rstd * ga + be, 0.f);
        v.z = fmaxf((v.z - mu) * rstd * ga + be, 0.f);
        v.w = fmaxf((v.w - mu) * rstd * ga + be, 0.f);
        b4[i] = v;
    }
}

// ---------------------------------------------------------------------------
extern "C" void kernel_launch(void* const* d_in, const int* in_sizes, int n_in,
                              void* d_out, int out_size) {
    const float* x      = (const float*)d_in[0];
    const float* offset = (const float*)d_in[1];
    const float* mask   = (const float*)d_in[2];
    const float* weight = (const float*)d_in[3];
    const float* bias   = (const float*)d_in[4];
    const float* gamma  = (const float*)d_in[5];
    const float* beta   = (const float*)d_in[6];
    float* out = (float*)d_out;

    cudaFuncSetAttribute(k_conv, cudaFuncAttributeMaxDynamicSharedMemorySize, SMEM_DYN);

    k_prep_x<<<dim3(128, 8, 4), dim3(32, 8)>>>(x);
    k_prep_w<<<NCHUNK, 256>>>(weight);
    k_prep_params<<<576, 256>>>(offset, mask);
    k_conv<<<256, 256, SMEM_DYN>>>(bias, out);
    k_gn<<<128, 256>>>(out, gamma, beta);
}